// round 7
// baseline (speedup 1.0000x reference)
#include <cuda_runtime.h>
#include <cuda_bf16.h>
#include <cstdint>

#define NSUB 8192
#define OUTN 4761
#define TLEN 4096
#define NWPAD 4864          // OUTN padded to multiple of 128 (zero rows)
#define NTILES 38           // NWPAD / 128
#define NT_PER_CTA 19

// bf16 split-2 operands: value = hi + lo (each bf16), [row][k] with k=0..63
__device__ __align__(16) __nv_bfloat16 g_hhi[NSUB * 64];
__device__ __align__(16) __nv_bfloat16 g_hlo[NSUB * 64];
__device__ __align__(16) __nv_bfloat16 g_whi[NWPAD * 64];
__device__ __align__(16) __nv_bfloat16 g_wlo[NWPAD * 64];
// Convergence export: the period-2 pair + first unwritten row + parity
__device__ float g_rowA[64];
__device__ float g_rowB[64];
__device__ int   g_r0;
__device__ int   g_ipar;

__device__ __forceinline__ uint32_t smem_u32(const void* p) {
    uint32_t a;
    asm("{ .reg .u64 t; cvta.to.shared.u64 t, %1; cvt.u32.u64 %0, t; }"
        : "=r"(a) : "l"(p));
    return a;
}
__device__ __forceinline__ void bf16_split(float v, __nv_bfloat16& hi, __nv_bfloat16& lo) {
    hi = __float2bfloat16(v);
    lo = __float2bfloat16(v - __bfloat162float(hi));
}
__device__ __forceinline__ void cp16(uint32_t dst, const void* src) {
    asm volatile("cp.async.cg.shared.global [%0], [%1], 16;"
                 :: "r"(dst), "l"(src) : "memory");
}
#define CP_COMMIT()  asm volatile("cp.async.commit_group;" ::: "memory")
#define CP_WAIT(n)   asm volatile("cp.async.wait_group %0;" :: "n"(n) : "memory")
#define LDSM_X4(r0, r1, r2, r3, addr) \
    asm volatile("ldmatrix.sync.aligned.m8n8.x4.shared.b16 {%0,%1,%2,%3}, [%4];" \
                 : "=r"(r0), "=r"(r1), "=r"(r2), "=r"(r3) : "r"(addr))
#define MMA_BF16(d, a, b) \
    asm volatile("mma.sync.aligned.m16n8k16.row.col.f32.bf16.bf16.f32 " \
                 "{%0,%1,%2,%3}, {%4,%5,%6,%7}, {%8,%9}, {%0,%1,%2,%3};" \
                 : "+f"((d)[0]), "+f"((d)[1]), "+f"((d)[2]), "+f"((d)[3]) \
                 : "r"((a)[0]), "r"((a)[1]), "r"((a)[2]), "r"((a)[3]), \
                   "r"((b)[0]), "r"((b)[1]))

// ---------------------------------------------------------------------------
// Phase 1: serial recurrence; emits bf16 (hi,lo) rows. ONE fused barrier per
// iteration: __syncthreads_and doubles as the step barrier and the period-2
// vote. The vote at iter i compares the staggered state T=(h0[i-1],h1[i-2])
// against T two steps earlier — all slots involved were written in earlier
// iterations, so the pre-barrier reads are race-free (iter i writes slots
// i&3 of ring0 and (i-1)&3 of ring1 only).
// ---------------------------------------------------------------------------
__global__ void __launch_bounds__(256, 1) rnn_phase1(
    const float* __restrict__ hidden,
    const float* __restrict__ W_hh0,
    const float* __restrict__ b_ih0,
    const float* __restrict__ b_hh0,
    const float* __restrict__ W_ih1,
    const float* __restrict__ W_hh1,
    const float* __restrict__ b_ih1,
    const float* __restrict__ b_hh1)
{
    __shared__ __align__(16) float ring0[4][64];
    __shared__ __align__(16) float ring1[4][64];

    const int tid = threadIdx.x;
    if (tid == 0) g_r0 = NSUB;
    if (tid < 64) {
        ring0[0][tid] = hidden[tid];
        ring1[0][tid] = hidden[64 + tid];
    }

    const bool g0 = (tid < 128);
    const int t = g0 ? tid : (tid - 128);
    const int o = t >> 1;
    const int half = t & 1;

    float wa[32], wb[32];
    float cb;
    if (g0) {
        const float* wrow = W_hh0 + o * 64 + half * 32;
#pragma unroll
        for (int j = 0; j < 32; ++j) wa[j] = wrow[j];
        cb = b_ih0[o] + b_hh0[o];
    } else {
        const float* wrow1 = W_ih1 + o * 64 + half * 32;
        const float* wrow2 = W_hh1 + o * 64 + half * 32;
#pragma unroll
        for (int j = 0; j < 32; ++j) { wa[j] = wrow1[j]; wb[j] = wrow2[j]; }
        cb = b_ih1[o] + b_hh1[o];
    }
    __syncthreads();

    for (int i = 1; i <= NSUB + 1; ++i) {
        // --- vote input (reads only slots from iterations <= i-1) ---
        int eq = 0;
        if (i >= 10) {
            eq = 1;
            if (tid < 64) {
                float d = fabsf(ring0[(i - 1) & 3][tid] - ring0[(i - 3) & 3][tid]);
                eq = (d < 1e-5f);
            } else if (tid < 128) {
                float d = fabsf(ring1[(i - 2) & 3][tid - 64] - ring1[(i - 4) & 3][tid - 64]);
                eq = (d < 1e-5f);
            }
        }
        // --- step i ---
        if (g0) {
            if (i <= NSUB) {
                const float4* h = (const float4*)(ring0[(i - 1) & 3] + half * 32);
                float a0 = 0.f, a1 = 0.f, a2 = 0.f, a3 = 0.f;
#pragma unroll
                for (int j = 0; j < 8; ++j) {
                    float4 hv = h[j];
                    a0 = fmaf(wa[4 * j + 0], hv.x, a0);
                    a1 = fmaf(wa[4 * j + 1], hv.y, a1);
                    a2 = fmaf(wa[4 * j + 2], hv.z, a2);
                    a3 = fmaf(wa[4 * j + 3], hv.w, a3);
                }
                float s = (a0 + a1) + (a2 + a3);
                s += __shfl_xor_sync(0xffffffffu, s, 1);
                if (half == 0) ring0[i & 3][o] = tanhf(s + cb);
            }
        } else {
            if (i >= 2) {
                const float4* hp0 = (const float4*)(ring0[(i - 1) & 3] + half * 32);
                const float4* hp1 = (const float4*)(ring1[(i - 2) & 3] + half * 32);
                float a0 = 0.f, a1 = 0.f, a2 = 0.f, a3 = 0.f;
#pragma unroll
                for (int j = 0; j < 8; ++j) {
                    float4 u = hp0[j];
                    float4 v = hp1[j];
                    a0 = fmaf(wa[4 * j + 0], u.x, a0);
                    a1 = fmaf(wa[4 * j + 1], u.y, a1);
                    a2 = fmaf(wa[4 * j + 2], u.z, a2);
                    a3 = fmaf(wa[4 * j + 3], u.w, a3);
                    a0 = fmaf(wb[4 * j + 0], v.x, a0);
                    a1 = fmaf(wb[4 * j + 1], v.y, a1);
                    a2 = fmaf(wb[4 * j + 2], v.z, a2);
                    a3 = fmaf(wb[4 * j + 3], v.w, a3);
                }
                float s = (a0 + a1) + (a2 + a3);
                s += __shfl_xor_sync(0xffffffffu, s, 1);
                if (half == 0) {
                    float val = tanhf(s + cb);
                    ring1[(i - 1) & 3][o] = val;
                    __nv_bfloat16 hi, lo;
                    bf16_split(val, hi, lo);
                    g_hhi[(i - 2) * 64 + o] = hi;
                    g_hlo[(i - 2) * 64 + o] = lo;
                }
            }
        }
        // --- fused barrier + vote ---
        if (__syncthreads_and(eq)) {
            // T_{i-1}==T_{i-3} => h1 period-2 for indices >= i-4.
            // ring1[(i-1)&3]=h1[i-1] (just written), ring1[(i-2)&3]=h1[i-2].
            if (tid < 64) {
                g_rowA[tid] = ring1[(i - 1) & 3][tid];
                g_rowB[tid] = ring1[(i - 2) & 3][tid];
            }
            if (tid == 0) { g_r0 = i - 1; g_ipar = i & 1; }
            return;
        }
    }
}

// ---------------------------------------------------------------------------
__global__ void __launch_bounds__(256) convert_w(const float* __restrict__ W_lin)
{
    int idx = blockIdx.x * 256 + threadIdx.x;
    if (idx >= NWPAD * 64) return;
    int n = idx >> 6, k = idx & 63;
    float v = (n < OUTN) ? W_lin[n * 64 + k] : 0.f;
    __nv_bfloat16 hi, lo;
    bf16_split(v, hi, lo);
    g_whi[idx] = hi;
    g_wlo[idx] = lo;
}

// ---------------------------------------------------------------------------
__global__ void __launch_bounds__(256) fill_kernel()
{
    const int r0 = g_r0;
    if (r0 >= NSUB) return;
    const int ip = g_ipar;
    const int total = (NSUB - r0) * 64;
    for (int idx = blockIdx.x * 256 + threadIdx.x; idx < total;
         idx += gridDim.x * 256) {
        int r = r0 + (idx >> 6);
        int k = idx & 63;
        float v = ((r & 1) == ip) ? g_rowA[k] : g_rowB[k];
        __nv_bfloat16 hi, lo;
        bf16_split(v, hi, lo);
        g_hhi[r * 64 + k] = hi;
        g_hlo[r * 64 + k] = lo;
    }
}

// ---------------------------------------------------------------------------
// Phase 2: persistent-tile tensor GEMM.
// 128 CTAs (64 m-blocks x 2 halves), 1 CTA/SM. Each CTA loads its A tile
// (hi+lo, 32KB) once, then iterates over 19 N-tiles with cp.async
// double-buffered B (2 x 32KB). D = Ahi*Bhi + Ahi*Blo + Alo*Bhi via
// mma.sync bf16, bias in accumulator init, direct STG epilogue with the
// (m&1, m>>1) output-row permutation.
// ---------------------------------------------------------------------------
#define SM_A_HI  0
#define SM_A_LO  16384
#define SM_B0    32768          // buf s at 32768 + s*32768; lo at +16384
#define SM_TOTAL (32768 + 2 * 32768)

__global__ void __launch_bounds__(256, 1) proj_mma(
    const float* __restrict__ b_lin,
    float* __restrict__ out)
{
    extern __shared__ char smem[];
    const uint32_t sb = smem_u32(smem);
    const int tid = threadIdx.x;
    const int m0 = (blockIdx.x >> 1) * 128;
    const int jbase = (blockIdx.x & 1) * NT_PER_CTA;

    // ---- A tile (hi+lo), loaded once, XOR-swizzled ----
    {
        const int4* s0 = (const int4*)g_hhi + m0 * 8;
        const int4* s1 = (const int4*)g_hlo + m0 * 8;
#pragma unroll
        for (int it = 0; it < 4; ++it) {
            int f = tid + it * 256;     // 0..1023
            int row = f >> 3;
            int c = f & 7;
            int sw = row * 128 + ((c ^ (row & 7)) << 4);
            *(int4*)(smem + SM_A_HI + sw) = s0[row * 8 + c];
            *(int4*)(smem + SM_A_LO + sw) = s1[row * 8 + c];
        }
    }

    // ---- B tile prefetch (cp.async) ----
    auto loadB = [&](int j, int buf) {
        int n0 = (jbase + j) * 128;
        const int4* s2 = (const int4*)g_whi + n0 * 8;
        const int4* s3 = (const int4*)g_wlo + n0 * 8;
        uint32_t dh = sb + SM_B0 + buf * 32768;
#pragma unroll
        for (int it = 0; it < 4; ++it) {
            int f = tid + it * 256;
            int row = f >> 3;
            int c = f & 7;
            uint32_t sw = row * 128 + ((c ^ (row & 7)) << 4);
            cp16(dh + sw, s2 + row * 8 + c);
            cp16(dh + 16384 + sw, s3 + row * 8 + c);
        }
    };

    loadB(0, 0);
    CP_COMMIT();

    const int w = tid >> 5, lane = tid & 31;
    const int wm = w & 1;
    const int wn = w >> 1;
    const int lq = lane >> 2;
    const int lr = lane & 3;

    const int a_row = ((lane >> 3) & 1) * 8 + (lane & 7);
    const int a_cadd = lane >> 4;
    const int b_row = ((lane >> 4) & 1) * 8 + (lane & 7);
    const int b_cadd = (lane >> 3) & 1;

    for (int j = 0; j < NT_PER_CTA; ++j) {
        if (j + 1 < NT_PER_CTA) {
            loadB(j + 1, (j + 1) & 1);
            CP_COMMIT();
            CP_WAIT(1);
        } else {
            CP_WAIT(0);
        }
        __syncthreads();

        const int n0 = (jbase + j) * 128;

        // accumulators with bias folded in
        float d[4][4][4];
#pragma unroll
        for (int nf = 0; nf < 4; ++nf) {
            int c = n0 + wn * 32 + nf * 8 + lr * 2;
            float b0v = (c < OUTN) ? b_lin[c] : 0.f;
            float b1v = (c + 1 < OUTN) ? b_lin[c + 1] : 0.f;
#pragma unroll
            for (int mf = 0; mf < 4; ++mf) {
                d[mf][nf][0] = b0v; d[mf][nf][1] = b1v;
                d[mf][nf][2] = b0v; d[mf][nf][3] = b1v;
            }
        }

        const uint32_t bB = sb + SM_B0 + (j & 1) * 32768;
#pragma unroll
        for (int ks = 0; ks < 4; ++ks) {
            uint32_t bh[4][2], bl[4][2];
#pragma unroll
            for (int g = 0; g < 2; ++g) {
                int nrow = wn * 32 + g * 16 + b_row;
                int chunk = 2 * ks + b_cadd;
                uint32_t addr = bB + nrow * 128 + ((chunk ^ (nrow & 7)) << 4);
                LDSM_X4(bh[2 * g][0], bh[2 * g][1], bh[2 * g + 1][0], bh[2 * g + 1][1], addr);
                LDSM_X4(bl[2 * g][0], bl[2 * g][1], bl[2 * g + 1][0], bl[2 * g + 1][1],
                        addr + 16384);
            }
#pragma unroll
            for (int mf = 0; mf < 4; ++mf) {
                int mrow = wm * 64 + mf * 16 + a_row;
                int chunk = 2 * ks + a_cadd;
                uint32_t addr = sb + SM_A_HI + mrow * 128 + ((chunk ^ (mrow & 7)) << 4);
                uint32_t ah[4], al[4];
                LDSM_X4(ah[0], ah[1], ah[2], ah[3], addr);
                LDSM_X4(al[0], al[1], al[2], al[3], addr + 16384);
                // 3 passes over nf: same-accumulator reuse distance = 4
#pragma unroll
                for (int nf = 0; nf < 4; ++nf) MMA_BF16(d[mf][nf], ah, bh[nf]);
#pragma unroll
                for (int nf = 0; nf < 4; ++nf) MMA_BF16(d[mf][nf], ah, bl[nf]);
#pragma unroll
                for (int nf = 0; nf < 4; ++nf) MMA_BF16(d[mf][nf], al, bh[nf]);
            }
        }
        __syncthreads();   // all reads of buf (j&1) done before it is refilled

        // epilogue: direct stores with the (m&1, m>>1) row permutation
#pragma unroll
        for (int mf = 0; mf < 4; ++mf) {
            int m1 = m0 + wm * 64 + mf * 16 + lq;
            int m2 = m1 + 8;
            long base1 = (long)((m1 & 1) * TLEN + (m1 >> 1)) * OUTN;
            long base2 = (long)((m2 & 1) * TLEN + (m2 >> 1)) * OUTN;
#pragma unroll
            for (int nf = 0; nf < 4; ++nf) {
                int c = n0 + wn * 32 + nf * 8 + lr * 2;
                if (c + 1 < OUTN) {
                    out[base1 + c]     = d[mf][nf][0];
                    out[base1 + c + 1] = d[mf][nf][1];
                    out[base2 + c]     = d[mf][nf][2];
                    out[base2 + c + 1] = d[mf][nf][3];
                } else if (c < OUTN) {
                    out[base1 + c] = d[mf][nf][0];
                    out[base2 + c] = d[mf][nf][2];
                }
            }
        }
    }
}

// ---------------------------------------------------------------------------
extern "C" void kernel_launch(void* const* d_in, const int* in_sizes, int n_in,
                              void* d_out, int out_size)
{
    (void)in_sizes; (void)n_in; (void)out_size;
    const float* hidden = (const float*)d_in[0];
    const float* W_hh0  = (const float*)d_in[2];
    const float* b_ih0  = (const float*)d_in[3];
    const float* b_hh0  = (const float*)d_in[4];
    const float* W_ih1  = (const float*)d_in[5];
    const float* W_hh1  = (const float*)d_in[6];
    const float* b_ih1  = (const float*)d_in[7];
    const float* b_hh1  = (const float*)d_in[8];
    const float* W_lin  = (const float*)d_in[9];
    const float* b_lin  = (const float*)d_in[10];
    float* out = (float*)d_out;

    cudaFuncSetAttribute(proj_mma,
                         cudaFuncAttributeMaxDynamicSharedMemorySize, SM_TOTAL);

    convert_w<<<(NWPAD * 64 + 255) / 256, 256>>>(W_lin);
    rnn_phase1<<<1, 256>>>(hidden, W_hh0, b_ih0, b_hh0,
                           W_ih1, W_hh1, b_ih1, b_hh1);
    fill_kernel<<<1024, 256>>>();

    proj_mma<<<128, 256, SM_TOTAL>>>(b_lin, out);
}

// round 8
// speedup vs baseline: 1.2443x; 1.2443x over previous
#include <cuda_runtime.h>
#include <cuda_bf16.h>
#include <cstdint>

#define NSUB 8192
#define OUTN 4761
#define TLEN 4096
#define NWPAD 4864          // OUTN padded to multiple of 128 (zero rows)

// bf16 split-2 operands: value = hi + lo (each bf16), [row][k] with k=0..63
__device__ __align__(16) __nv_bfloat16 g_hhi[NSUB * 64];
__device__ __align__(16) __nv_bfloat16 g_hlo[NSUB * 64];
__device__ __align__(16) __nv_bfloat16 g_whi[NWPAD * 64];
__device__ __align__(16) __nv_bfloat16 g_wlo[NWPAD * 64];
// Convergence export: the period-2 pair + first unwritten row + parity
__device__ float g_rowA[64];
__device__ float g_rowB[64];
__device__ int   g_r0;
__device__ int   g_ipar;

__device__ __forceinline__ uint32_t smem_u32(const void* p) {
    uint32_t a;
    asm("{ .reg .u64 t; cvta.to.shared.u64 t, %1; cvt.u32.u64 %0, t; }"
        : "=r"(a) : "l"(p));
    return a;
}
__device__ __forceinline__ void bf16_split(float v, __nv_bfloat16& hi, __nv_bfloat16& lo) {
    hi = __float2bfloat16(v);
    lo = __float2bfloat16(v - __bfloat162float(hi));
}
__device__ __forceinline__ void cp16(uint32_t dst, const void* src) {
    asm volatile("cp.async.cg.shared.global [%0], [%1], 16;"
                 :: "r"(dst), "l"(src) : "memory");
}
#define CP_COMMIT()  asm volatile("cp.async.commit_group;" ::: "memory")
#define CP_WAIT(n)   asm volatile("cp.async.wait_group %0;" :: "n"(n) : "memory")
#define LDSM_X4(r0, r1, r2, r3, addr) \
    asm volatile("ldmatrix.sync.aligned.m8n8.x4.shared.b16 {%0,%1,%2,%3}, [%4];" \
                 : "=r"(r0), "=r"(r1), "=r"(r2), "=r"(r3) : "r"(addr))
#define MMA_BF16(d, a, b) \
    asm volatile("mma.sync.aligned.m16n8k16.row.col.f32.bf16.bf16.f32 " \
                 "{%0,%1,%2,%3}, {%4,%5,%6,%7}, {%8,%9}, {%0,%1,%2,%3};" \
                 : "+f"((d)[0]), "+f"((d)[1]), "+f"((d)[2]), "+f"((d)[3]) \
                 : "r"((a)[0]), "r"((a)[1]), "r"((a)[2]), "r"((a)[3]), \
                   "r"((b)[0]), "r"((b)[1]))

// ---------------------------------------------------------------------------
// Phase 1: serial recurrence; emits bf16 (hi,lo) rows. ONE fused barrier per
// iteration: __syncthreads_and doubles as the step barrier and the period-2
// vote (vote reads only slots written in earlier iterations -> race-free).
// ---------------------------------------------------------------------------
__global__ void __launch_bounds__(256, 1) rnn_phase1(
    const float* __restrict__ hidden,
    const float* __restrict__ W_hh0,
    const float* __restrict__ b_ih0,
    const float* __restrict__ b_hh0,
    const float* __restrict__ W_ih1,
    const float* __restrict__ W_hh1,
    const float* __restrict__ b_ih1,
    const float* __restrict__ b_hh1)
{
    __shared__ __align__(16) float ring0[4][64];
    __shared__ __align__(16) float ring1[4][64];

    const int tid = threadIdx.x;
    if (tid == 0) g_r0 = NSUB;
    if (tid < 64) {
        ring0[0][tid] = hidden[tid];
        ring1[0][tid] = hidden[64 + tid];
    }

    const bool g0 = (tid < 128);
    const int t = g0 ? tid : (tid - 128);
    const int o = t >> 1;
    const int half = t & 1;

    float wa[32], wb[32];
    float cb;
    if (g0) {
        const float* wrow = W_hh0 + o * 64 + half * 32;
#pragma unroll
        for (int j = 0; j < 32; ++j) wa[j] = wrow[j];
        cb = b_ih0[o] + b_hh0[o];
    } else {
        const float* wrow1 = W_ih1 + o * 64 + half * 32;
        const float* wrow2 = W_hh1 + o * 64 + half * 32;
#pragma unroll
        for (int j = 0; j < 32; ++j) { wa[j] = wrow1[j]; wb[j] = wrow2[j]; }
        cb = b_ih1[o] + b_hh1[o];
    }
    __syncthreads();

    for (int i = 1; i <= NSUB + 1; ++i) {
        int eq = 0;
        if (i >= 10) {
            eq = 1;
            if (tid < 64) {
                float d = fabsf(ring0[(i - 1) & 3][tid] - ring0[(i - 3) & 3][tid]);
                eq = (d < 1e-5f);
            } else if (tid < 128) {
                float d = fabsf(ring1[(i - 2) & 3][tid - 64] - ring1[(i - 4) & 3][tid - 64]);
                eq = (d < 1e-5f);
            }
        }
        if (g0) {
            if (i <= NSUB) {
                const float4* h = (const float4*)(ring0[(i - 1) & 3] + half * 32);
                float a0 = 0.f, a1 = 0.f, a2 = 0.f, a3 = 0.f;
#pragma unroll
                for (int j = 0; j < 8; ++j) {
                    float4 hv = h[j];
                    a0 = fmaf(wa[4 * j + 0], hv.x, a0);
                    a1 = fmaf(wa[4 * j + 1], hv.y, a1);
                    a2 = fmaf(wa[4 * j + 2], hv.z, a2);
                    a3 = fmaf(wa[4 * j + 3], hv.w, a3);
                }
                float s = (a0 + a1) + (a2 + a3);
                s += __shfl_xor_sync(0xffffffffu, s, 1);
                if (half == 0) ring0[i & 3][o] = tanhf(s + cb);
            }
        } else {
            if (i >= 2) {
                const float4* hp0 = (const float4*)(ring0[(i - 1) & 3] + half * 32);
                const float4* hp1 = (const float4*)(ring1[(i - 2) & 3] + half * 32);
                float a0 = 0.f, a1 = 0.f, a2 = 0.f, a3 = 0.f;
#pragma unroll
                for (int j = 0; j < 8; ++j) {
                    float4 u = hp0[j];
                    float4 v = hp1[j];
                    a0 = fmaf(wa[4 * j + 0], u.x, a0);
                    a1 = fmaf(wa[4 * j + 1], u.y, a1);
                    a2 = fmaf(wa[4 * j + 2], u.z, a2);
                    a3 = fmaf(wa[4 * j + 3], u.w, a3);
                    a0 = fmaf(wb[4 * j + 0], v.x, a0);
                    a1 = fmaf(wb[4 * j + 1], v.y, a1);
                    a2 = fmaf(wb[4 * j + 2], v.z, a2);
                    a3 = fmaf(wb[4 * j + 3], v.w, a3);
                }
                float s = (a0 + a1) + (a2 + a3);
                s += __shfl_xor_sync(0xffffffffu, s, 1);
                if (half == 0) {
                    float val = tanhf(s + cb);
                    ring1[(i - 1) & 3][o] = val;
                    __nv_bfloat16 hi, lo;
                    bf16_split(val, hi, lo);
                    g_hhi[(i - 2) * 64 + o] = hi;
                    g_hlo[(i - 2) * 64 + o] = lo;
                }
            }
        }
        if (__syncthreads_and(eq)) {
            if (tid < 64) {
                g_rowA[tid] = ring1[(i - 1) & 3][tid];
                g_rowB[tid] = ring1[(i - 2) & 3][tid];
            }
            if (tid == 0) { g_r0 = i - 1; g_ipar = i & 1; }
            return;
        }
    }
}

// ---------------------------------------------------------------------------
__global__ void __launch_bounds__(256) convert_w(const float* __restrict__ W_lin)
{
    int idx = blockIdx.x * 256 + threadIdx.x;
    if (idx >= NWPAD * 64) return;
    int n = idx >> 6, k = idx & 63;
    float v = (n < OUTN) ? W_lin[n * 64 + k] : 0.f;
    __nv_bfloat16 hi, lo;
    bf16_split(v, hi, lo);
    g_whi[idx] = hi;
    g_wlo[idx] = lo;
}

// ---------------------------------------------------------------------------
__global__ void __launch_bounds__(256) fill_kernel()
{
    const int r0 = g_r0;
    if (r0 >= NSUB) return;
    const int ip = g_ipar;
    const int total = (NSUB - r0) * 64;
    for (int idx = blockIdx.x * 256 + threadIdx.x; idx < total;
         idx += gridDim.x * 256) {
        int r = r0 + (idx >> 6);
        int k = idx & 63;
        float v = ((r & 1) == ip) ? g_rowA[k] : g_rowB[k];
        __nv_bfloat16 hi, lo;
        bf16_split(v, hi, lo);
        g_hhi[r * 64 + k] = hi;
        g_hlo[r * 64 + k] = lo;
    }
}

// ---------------------------------------------------------------------------
// Phase 2 (tensor, grid-tiled as in R6, + cp.async k-chunk pipeline):
// per 128x128 tile, D = Ahi*Bhi^T + Ahi*Blo^T + Alo*Bhi^T (fp32 accum).
// The 4 k-step chunks (16KB each: 2 16B chunks/row x 128 rows x 4 tiles) are
// issued as 4 cp.async commit groups up front; each k-step's MMAs wait only
// for its own group. 8 warps (2m x 4n), warp tile 64x32, XOR-swizzled smem.
// ---------------------------------------------------------------------------
#define SM_A_HI  0
#define SM_A_LO  16384
#define SM_B_HI  32768
#define SM_B_LO  49152
#define SM_TOTAL 65536

__global__ void __launch_bounds__(256, 2) proj_mma(
    const float* __restrict__ b_lin,
    float* __restrict__ out)
{
    extern __shared__ char smem[];
    const uint32_t sb = smem_u32(smem);
    const int tid = threadIdx.x;
    const int m0 = blockIdx.y * 128;
    const int n0 = blockIdx.x * 128;

    // ---- issue all 4 k-chunk groups up front ----
    {
        const int row = tid >> 1;            // 0..127
        const int csub = tid & 1;
        const int4* sAh = (const int4*)g_hhi + (m0 + row) * 8;
        const int4* sAl = (const int4*)g_hlo + (m0 + row) * 8;
        const int4* sBh = (const int4*)g_whi + (n0 + row) * 8;
        const int4* sBl = (const int4*)g_wlo + (n0 + row) * 8;
#pragma unroll
        for (int ks = 0; ks < 4; ++ks) {
            int c = 2 * ks + csub;
            uint32_t sw = row * 128 + ((c ^ (row & 7)) << 4);
            cp16(sb + SM_A_HI + sw, sAh + c);
            cp16(sb + SM_A_LO + sw, sAl + c);
            cp16(sb + SM_B_HI + sw, sBh + c);
            cp16(sb + SM_B_LO + sw, sBl + c);
            CP_COMMIT();
        }
    }

    const int w = tid >> 5, lane = tid & 31;
    const int wm = w & 1;          // 2 warps along M
    const int wn = w >> 1;         // 4 warps along N
    const int lq = lane >> 2;
    const int lr = lane & 3;

    // accumulators with bias folded in (loads overlap the cp.async groups)
    float d[4][4][4];
#pragma unroll
    for (int nf = 0; nf < 4; ++nf) {
        int c = n0 + wn * 32 + nf * 8 + lr * 2;
        float b0v = (c < OUTN) ? b_lin[c] : 0.f;
        float b1v = (c + 1 < OUTN) ? b_lin[c + 1] : 0.f;
#pragma unroll
        for (int mf = 0; mf < 4; ++mf) {
            d[mf][nf][0] = b0v; d[mf][nf][1] = b1v;
            d[mf][nf][2] = b0v; d[mf][nf][3] = b1v;
        }
    }

    const int a_row = ((lane >> 3) & 1) * 8 + (lane & 7);
    const int a_cadd = lane >> 4;
    const int b_row = ((lane >> 4) & 1) * 8 + (lane & 7);
    const int b_cadd = (lane >> 3) & 1;

#pragma unroll
    for (int ks = 0; ks < 4; ++ks) {
        if (ks == 0)      CP_WAIT(3);
        else if (ks == 1) CP_WAIT(2);
        else if (ks == 2) CP_WAIT(1);
        else              CP_WAIT(0);
        __syncthreads();

        uint32_t bh[4][2], bl[4][2];
#pragma unroll
        for (int g = 0; g < 2; ++g) {
            int nrow = wn * 32 + g * 16 + b_row;
            int chunk = 2 * ks + b_cadd;
            uint32_t addr = sb + SM_B_HI + nrow * 128 + ((chunk ^ (nrow & 7)) << 4);
            LDSM_X4(bh[2 * g][0], bh[2 * g][1], bh[2 * g + 1][0], bh[2 * g + 1][1], addr);
            LDSM_X4(bl[2 * g][0], bl[2 * g][1], bl[2 * g + 1][0], bl[2 * g + 1][1],
                    addr + 16384);
        }
#pragma unroll
        for (int mf = 0; mf < 4; ++mf) {
            int mrow = wm * 64 + mf * 16 + a_row;
            int chunk = 2 * ks + a_cadd;
            uint32_t addr = sb + SM_A_HI + mrow * 128 + ((chunk ^ (mrow & 7)) << 4);
            uint32_t ah[4], al[4];
            LDSM_X4(ah[0], ah[1], ah[2], ah[3], addr);
            LDSM_X4(al[0], al[1], al[2], al[3], addr + 16384);
#pragma unroll
            for (int nf = 0; nf < 4; ++nf) MMA_BF16(d[mf][nf], ah, bh[nf]);
#pragma unroll
            for (int nf = 0; nf < 4; ++nf) MMA_BF16(d[mf][nf], ah, bl[nf]);
#pragma unroll
            for (int nf = 0; nf < 4; ++nf) MMA_BF16(d[mf][nf], al, bh[nf]);
        }
    }

    // ---- epilogue: direct stores with the (m&1, m>>1) row permutation ----
#pragma unroll
    for (int mf = 0; mf < 4; ++mf) {
        int m1 = m0 + wm * 64 + mf * 16 + lq;
        int m2 = m1 + 8;
        long base1 = (long)((m1 & 1) * TLEN + (m1 >> 1)) * OUTN;
        long base2 = (long)((m2 & 1) * TLEN + (m2 >> 1)) * OUTN;
#pragma unroll
        for (int nf = 0; nf < 4; ++nf) {
            int c = n0 + wn * 32 + nf * 8 + lr * 2;
            if (c + 1 < OUTN) {
                out[base1 + c]     = d[mf][nf][0];
                out[base1 + c + 1] = d[mf][nf][1];
                out[base2 + c]     = d[mf][nf][2];
                out[base2 + c + 1] = d[mf][nf][3];
            } else if (c < OUTN) {
                out[base1 + c] = d[mf][nf][0];
                out[base2 + c] = d[mf][nf][2];
            }
        }
    }
}

// ---------------------------------------------------------------------------
extern "C" void kernel_launch(void* const* d_in, const int* in_sizes, int n_in,
                              void* d_out, int out_size)
{
    (void)in_sizes; (void)n_in; (void)out_size;
    const float* hidden = (const float*)d_in[0];
    const float* W_hh0  = (const float*)d_in[2];
    const float* b_ih0  = (const float*)d_in[3];
    const float* b_hh0  = (const float*)d_in[4];
    const float* W_ih1  = (const float*)d_in[5];
    const float* W_hh1  = (const float*)d_in[6];
    const float* b_ih1  = (const float*)d_in[7];
    const float* b_hh1  = (const float*)d_in[8];
    const float* W_lin  = (const float*)d_in[9];
    const float* b_lin  = (const float*)d_in[10];
    float* out = (float*)d_out;

    cudaFuncSetAttribute(proj_mma,
                         cudaFuncAttributeMaxDynamicSharedMemorySize, SM_TOTAL);

    convert_w<<<(NWPAD * 64 + 255) / 256, 256>>>(W_lin);
    rnn_phase1<<<1, 256>>>(hidden, W_hh0, b_ih0, b_hh0,
                           W_ih1, W_hh1, b_ih1, b_hh1);
    fill_kernel<<<1024, 256>>>();

    dim3 grid(NWPAD / 128, NSUB / 128);
    proj_mma<<<grid, 256, SM_TOTAL>>>(b_lin, out);
}

// round 10
// speedup vs baseline: 1.4468x; 1.1627x over previous
#include <cuda_runtime.h>
#include <cstdint>

#define NSUB 8192
#define OUTN 4761
#define TLEN 4096

// fp32 top-layer hidden states, row-major [n][64] (only rows < r0 used)
__device__ __align__(16) float g_h1[NSUB * 64];
// Convergence export
__device__ float g_rowA[64];   // h1[i-1]
__device__ float g_rowB[64];   // h1[i-2]
__device__ int   g_r0;         // first periodic row (NSUB if no convergence)
__device__ int   g_ipar;       // i & 1 at exit
// Projected periodic pair
__device__ __align__(16) float g_yA[OUTN];
__device__ __align__(16) float g_yB[OUTN];

// ---------------------------------------------------------------------------
// Phase 1: serial recurrence; fused barrier+vote period-2 early exit.
//   warps 0-3: h0[i] = tanh(c0 + W_hh0 h0[i-1])
//   warps 4-7: h1[i-1] = tanh(c1 + W_ih1 h0[i-1] + W_hh1 h1[i-2])
// Vote reads only ring slots written in earlier iterations -> race-free
// before the single __syncthreads_and per iteration.
// ---------------------------------------------------------------------------
__global__ void __launch_bounds__(256, 1) rnn_phase1(
    const float* __restrict__ hidden,
    const float* __restrict__ W_hh0,
    const float* __restrict__ b_ih0,
    const float* __restrict__ b_hh0,
    const float* __restrict__ W_ih1,
    const float* __restrict__ W_hh1,
    const float* __restrict__ b_ih1,
    const float* __restrict__ b_hh1)
{
    __shared__ __align__(16) float ring0[4][64];
    __shared__ __align__(16) float ring1[4][64];

    const int tid = threadIdx.x;
    if (tid == 0) g_r0 = NSUB;
    if (tid < 64) {
        ring0[0][tid] = hidden[tid];
        ring1[0][tid] = hidden[64 + tid];
    }

    const bool g0 = (tid < 128);
    const int t = g0 ? tid : (tid - 128);
    const int o = t >> 1;
    const int half = t & 1;

    float wa[32], wb[32];
    float cb;
    if (g0) {
        const float* wrow = W_hh0 + o * 64 + half * 32;
#pragma unroll
        for (int j = 0; j < 32; ++j) wa[j] = wrow[j];
        cb = b_ih0[o] + b_hh0[o];
    } else {
        const float* wrow1 = W_ih1 + o * 64 + half * 32;
        const float* wrow2 = W_hh1 + o * 64 + half * 32;
#pragma unroll
        for (int j = 0; j < 32; ++j) { wa[j] = wrow1[j]; wb[j] = wrow2[j]; }
        cb = b_ih1[o] + b_hh1[o];
    }
    __syncthreads();

    for (int i = 1; i <= NSUB + 1; ++i) {
        int eq = 0;
        if (i >= 10) {
            eq = 1;
            if (tid < 64) {
                float d = fabsf(ring0[(i - 1) & 3][tid] - ring0[(i - 3) & 3][tid]);
                eq = (d < 1e-5f);
            } else if (tid < 128) {
                float d = fabsf(ring1[(i - 2) & 3][tid - 64] - ring1[(i - 4) & 3][tid - 64]);
                eq = (d < 1e-5f);
            }
        }
        if (g0) {
            if (i <= NSUB) {
                const float4* h = (const float4*)(ring0[(i - 1) & 3] + half * 32);
                float a0 = 0.f, a1 = 0.f, a2 = 0.f, a3 = 0.f;
#pragma unroll
                for (int j = 0; j < 8; ++j) {
                    float4 hv = h[j];
                    a0 = fmaf(wa[4 * j + 0], hv.x, a0);
                    a1 = fmaf(wa[4 * j + 1], hv.y, a1);
                    a2 = fmaf(wa[4 * j + 2], hv.z, a2);
                    a3 = fmaf(wa[4 * j + 3], hv.w, a3);
                }
                float s = (a0 + a1) + (a2 + a3);
                s += __shfl_xor_sync(0xffffffffu, s, 1);
                if (half == 0) ring0[i & 3][o] = tanhf(s + cb);
            }
        } else {
            if (i >= 2) {
                const float4* hp0 = (const float4*)(ring0[(i - 1) & 3] + half * 32);
                const float4* hp1 = (const float4*)(ring1[(i - 2) & 3] + half * 32);
                float a0 = 0.f, a1 = 0.f, a2 = 0.f, a3 = 0.f;
#pragma unroll
                for (int j = 0; j < 8; ++j) {
                    float4 u = hp0[j];
                    float4 v = hp1[j];
                    a0 = fmaf(wa[4 * j + 0], u.x, a0);
                    a1 = fmaf(wa[4 * j + 1], u.y, a1);
                    a2 = fmaf(wa[4 * j + 2], u.z, a2);
                    a3 = fmaf(wa[4 * j + 3], u.w, a3);
                    a0 = fmaf(wb[4 * j + 0], v.x, a0);
                    a1 = fmaf(wb[4 * j + 1], v.y, a1);
                    a2 = fmaf(wb[4 * j + 2], v.z, a2);
                    a3 = fmaf(wb[4 * j + 3], v.w, a3);
                }
                float s = (a0 + a1) + (a2 + a3);
                s += __shfl_xor_sync(0xffffffffu, s, 1);
                if (half == 0) {
                    float val = tanhf(s + cb);
                    ring1[(i - 1) & 3][o] = val;
                    g_h1[(i - 2) * 64 + o] = val;   // row n holds h1[n+1]
                }
            }
        }
        if (__syncthreads_and(eq)) {
            if (tid < 64) {
                g_rowA[tid] = ring1[(i - 1) & 3][tid];
                g_rowB[tid] = ring1[(i - 2) & 3][tid];
            }
            if (tid == 0) { g_r0 = i - 1; g_ipar = i & 1; }
            return;
        }
    }
}

// ---------------------------------------------------------------------------
// Project the two periodic vectors: yA = rowA@W^T+b, yB = rowB@W^T+b.
// ---------------------------------------------------------------------------
__global__ void __launch_bounds__(256) yab_kernel(
    const float* __restrict__ W_lin,
    const float* __restrict__ b_lin)
{
    __shared__ float hA[64], hB[64];
    if (threadIdx.x < 64) hA[threadIdx.x] = g_rowA[threadIdx.x];
    else if (threadIdx.x < 128) hB[threadIdx.x - 64] = g_rowB[threadIdx.x - 64];
    __syncthreads();

    int p = blockIdx.x * 256 + threadIdx.x;
    if (p >= 2 * OUTN) return;
    int which = (p >= OUTN);
    int c = which ? (p - OUTN) : p;
    const float* h = which ? hB : hA;
    const float4* wr = (const float4*)(W_lin + c * 64);
    float acc = b_lin[c];
#pragma unroll
    for (int j = 0; j < 16; ++j) {
        float4 w = __ldg(wr + j);
        acc = fmaf(w.x, h[4 * j + 0], acc);
        acc = fmaf(w.y, h[4 * j + 1], acc);
        acc = fmaf(w.z, h[4 * j + 2], acc);
        acc = fmaf(w.w, h[4 * j + 3], acc);
    }
    if (which) g_yB[c] = acc; else g_yA[c] = acc;
}

// ---------------------------------------------------------------------------
// Exact projection for pre-convergence rows n < r0 (grid-stride over rows).
// ---------------------------------------------------------------------------
__global__ void __launch_bounds__(256) head_kernel(
    const float* __restrict__ W_lin,
    const float* __restrict__ b_lin,
    float* __restrict__ out)
{
    __shared__ float h[64];
    const int r0 = g_r0;
    for (int n = blockIdx.x; n < r0; n += gridDim.x) {
        __syncthreads();
        if (threadIdx.x < 64) h[threadIdx.x] = g_h1[n * 64 + threadIdx.x];
        __syncthreads();

        long base = (long)((n & 1) * TLEN + (n >> 1)) * OUTN;
        for (int c = threadIdx.x; c < OUTN; c += 256) {
            const float4* wr = (const float4*)(W_lin + c * 64);
            float acc = b_lin[c];
#pragma unroll
            for (int j = 0; j < 16; ++j) {
                float4 w = __ldg(wr + j);
                acc = fmaf(w.x, h[4 * j + 0], acc);
                acc = fmaf(w.y, h[4 * j + 1], acc);
                acc = fmaf(w.z, h[4 * j + 2], acc);
                acc = fmaf(w.w, h[4 * j + 3], acc);
            }
            out[base + c] = acc;
        }
    }
}

// ---------------------------------------------------------------------------
// Broadcast-fill: out[s][t][:] = (s==ipar ? yA : yB) for all n=2t+s >= r0.
// One block per output row; streaming float4 stores.
// ---------------------------------------------------------------------------
__global__ void __launch_bounds__(256) fill_out(float* __restrict__ out)
{
    const int t = blockIdx.x;        // 0..TLEN-1
    const int s = blockIdx.y;        // 0..1
    const int n = 2 * t + s;
    if (n < g_r0) return;

    __shared__ __align__(16) float ys[OUTN];
    const float* y = (s == g_ipar) ? g_yA : g_yB;
    for (int i = threadIdx.x; i < OUTN; i += 256) ys[i] = __ldg(y + i);
    __syncthreads();

    long base = (long)(s * TLEN + t) * OUTN;
    float* dst = out + base;
    const int a = (int)((4 - (base & 3)) & 3);   // leading scalars to align
    if (threadIdx.x < a) dst[threadIdx.x] = ys[threadIdx.x];
    const int nvec = (OUTN - a) >> 2;
    float4* dv = (float4*)(dst + a);
    for (int q = threadIdx.x; q < nvec; q += 256) {
        float4 v = make_float4(ys[a + 4 * q + 0], ys[a + 4 * q + 1],
                               ys[a + 4 * q + 2], ys[a + 4 * q + 3]);
        __stcs(dv + q, v);
    }
    const int tail = a + 4 * nvec;
    if (threadIdx.x < OUTN - tail) dst[tail + threadIdx.x] = ys[tail + threadIdx.x];
}

// ---------------------------------------------------------------------------
extern "C" void kernel_launch(void* const* d_in, const int* in_sizes, int n_in,
                              void* d_out, int out_size)
{
    (void)in_sizes; (void)n_in; (void)out_size;
    const float* hidden = (const float*)d_in[0];
    // d_in[1] = W_ih0: unused (RNN input is identically zero)
    const float* W_hh0  = (const float*)d_in[2];
    const float* b_ih0  = (const float*)d_in[3];
    const float* b_hh0  = (const float*)d_in[4];
    const float* W_ih1  = (const float*)d_in[5];
    const float* W_hh1  = (const float*)d_in[6];
    const float* b_ih1  = (const float*)d_in[7];
    const float* b_hh1  = (const float*)d_in[8];
    const float* W_lin  = (const float*)d_in[9];
    const float* b_lin  = (const float*)d_in[10];
    float* out = (float*)d_out;

    rnn_phase1<<<1, 256>>>(hidden, W_hh0, b_ih0, b_hh0,
                           W_ih1, W_hh1, b_ih1, b_hh1);

    yab_kernel<<<(2 * OUTN + 255) / 256, 256>>>(W_lin, b_lin);

    head_kernel<<<64, 256>>>(W_lin, b_lin, out);

    dim3 fgrid(TLEN, 2);
    fill_out<<<fgrid, 256>>>(out);
}

// round 11
// speedup vs baseline: 2.3842x; 1.6479x over previous
#include <cuda_runtime.h>
#include <cstdint>

#define NSUB 8192
#define OUTN 4761
#define TLEN 4096

// fp32 top-layer hidden states, row-major [n][64] (only rows < r0 used)
__device__ __align__(16) float g_h1[NSUB * 64];
// Convergence export
__device__ float g_rowA[64];   // h1[i-1]
__device__ float g_rowB[64];   // h1[i-2]
__device__ int   g_r0;         // first periodic row (NSUB if no convergence)
__device__ int   g_ipar;       // i & 1 at exit
// Projected periodic pair
__device__ __align__(16) float g_yA[OUTN];
__device__ __align__(16) float g_yB[OUTN];

// ---------------------------------------------------------------------------
// Phase 1: serial recurrence; fused barrier+vote period-2 early exit.
// ---------------------------------------------------------------------------
__global__ void __launch_bounds__(256, 1) rnn_phase1(
    const float* __restrict__ hidden,
    const float* __restrict__ W_hh0,
    const float* __restrict__ b_ih0,
    const float* __restrict__ b_hh0,
    const float* __restrict__ W_ih1,
    const float* __restrict__ W_hh1,
    const float* __restrict__ b_ih1,
    const float* __restrict__ b_hh1)
{
    __shared__ __align__(16) float ring0[4][64];
    __shared__ __align__(16) float ring1[4][64];

    const int tid = threadIdx.x;
    if (tid == 0) g_r0 = NSUB;
    if (tid < 64) {
        ring0[0][tid] = hidden[tid];
        ring1[0][tid] = hidden[64 + tid];
    }

    const bool g0 = (tid < 128);
    const int t = g0 ? tid : (tid - 128);
    const int o = t >> 1;
    const int half = t & 1;

    float wa[32], wb[32];
    float cb;
    if (g0) {
        const float* wrow = W_hh0 + o * 64 + half * 32;
#pragma unroll
        for (int j = 0; j < 32; ++j) wa[j] = wrow[j];
        cb = b_ih0[o] + b_hh0[o];
    } else {
        const float* wrow1 = W_ih1 + o * 64 + half * 32;
        const float* wrow2 = W_hh1 + o * 64 + half * 32;
#pragma unroll
        for (int j = 0; j < 32; ++j) { wa[j] = wrow1[j]; wb[j] = wrow2[j]; }
        cb = b_ih1[o] + b_hh1[o];
    }
    __syncthreads();

    for (int i = 1; i <= NSUB + 1; ++i) {
        int eq = 0;
        if (i >= 10) {
            eq = 1;
            if (tid < 64) {
                float d = fabsf(ring0[(i - 1) & 3][tid] - ring0[(i - 3) & 3][tid]);
                eq = (d < 1e-5f);
            } else if (tid < 128) {
                float d = fabsf(ring1[(i - 2) & 3][tid - 64] - ring1[(i - 4) & 3][tid - 64]);
                eq = (d < 1e-5f);
            }
        }
        if (g0) {
            if (i <= NSUB) {
                const float4* h = (const float4*)(ring0[(i - 1) & 3] + half * 32);
                float a0 = 0.f, a1 = 0.f, a2 = 0.f, a3 = 0.f;
#pragma unroll
                for (int j = 0; j < 8; ++j) {
                    float4 hv = h[j];
                    a0 = fmaf(wa[4 * j + 0], hv.x, a0);
                    a1 = fmaf(wa[4 * j + 1], hv.y, a1);
                    a2 = fmaf(wa[4 * j + 2], hv.z, a2);
                    a3 = fmaf(wa[4 * j + 3], hv.w, a3);
                }
                float s = (a0 + a1) + (a2 + a3);
                s += __shfl_xor_sync(0xffffffffu, s, 1);
                if (half == 0) ring0[i & 3][o] = tanhf(s + cb);
            }
        } else {
            if (i >= 2) {
                const float4* hp0 = (const float4*)(ring0[(i - 1) & 3] + half * 32);
                const float4* hp1 = (const float4*)(ring1[(i - 2) & 3] + half * 32);
                float a0 = 0.f, a1 = 0.f, a2 = 0.f, a3 = 0.f;
#pragma unroll
                for (int j = 0; j < 8; ++j) {
                    float4 u = hp0[j];
                    float4 v = hp1[j];
                    a0 = fmaf(wa[4 * j + 0], u.x, a0);
                    a1 = fmaf(wa[4 * j + 1], u.y, a1);
                    a2 = fmaf(wa[4 * j + 2], u.z, a2);
                    a3 = fmaf(wa[4 * j + 3], u.w, a3);
                    a0 = fmaf(wb[4 * j + 0], v.x, a0);
                    a1 = fmaf(wb[4 * j + 1], v.y, a1);
                    a2 = fmaf(wb[4 * j + 2], v.z, a2);
                    a3 = fmaf(wb[4 * j + 3], v.w, a3);
                }
                float s = (a0 + a1) + (a2 + a3);
                s += __shfl_xor_sync(0xffffffffu, s, 1);
                if (half == 0) {
                    float val = tanhf(s + cb);
                    ring1[(i - 1) & 3][o] = val;
                    g_h1[(i - 2) * 64 + o] = val;   // row n holds h1[n+1]
                }
            }
        }
        if (__syncthreads_and(eq)) {
            if (tid < 64) {
                g_rowA[tid] = ring1[(i - 1) & 3][tid];
                g_rowB[tid] = ring1[(i - 2) & 3][tid];
            }
            if (tid == 0) { g_r0 = i - 1; g_ipar = i & 1; }
            return;
        }
    }
}

// ---------------------------------------------------------------------------
// Project the two periodic vectors: yA = rowA@W^T+b, yB = rowB@W^T+b.
// ---------------------------------------------------------------------------
__global__ void __launch_bounds__(256) yab_kernel(
    const float* __restrict__ W_lin,
    const float* __restrict__ b_lin)
{
    __shared__ float hA[64], hB[64];
    if (threadIdx.x < 64) hA[threadIdx.x] = g_rowA[threadIdx.x];
    else if (threadIdx.x < 128) hB[threadIdx.x - 64] = g_rowB[threadIdx.x - 64];
    __syncthreads();

    int p = blockIdx.x * 256 + threadIdx.x;
    if (p >= 2 * OUTN) return;
    int which = (p >= OUTN);
    int c = which ? (p - OUTN) : p;
    const float* h = which ? hB : hA;
    const float4* wr = (const float4*)(W_lin + c * 64);
    float acc = b_lin[c];
#pragma unroll
    for (int j = 0; j < 16; ++j) {
        float4 w = __ldg(wr + j);
        acc = fmaf(w.x, h[4 * j + 0], acc);
        acc = fmaf(w.y, h[4 * j + 1], acc);
        acc = fmaf(w.z, h[4 * j + 2], acc);
        acc = fmaf(w.w, h[4 * j + 3], acc);
    }
    if (which) g_yB[c] = acc; else g_yA[c] = acc;
}

// ---------------------------------------------------------------------------
// Head: rows n < r0p (r0 padded to multiple of 8). Exact projection for
// n < r0; periodic copy (yA/yB) for [r0, r0p). Grid (19 col-chunks, rows).
// ---------------------------------------------------------------------------
__global__ void __launch_bounds__(256) head_kernel(
    const float* __restrict__ W_lin,
    const float* __restrict__ b_lin,
    float* __restrict__ out)
{
    const int r0 = g_r0;
    int r0p = (r0 + 7) & ~7;
    if (r0p > NSUB) r0p = NSUB;
    const int ip = g_ipar;

    const int c = blockIdx.x * 256 + threadIdx.x;
    if (c >= OUTN) return;

    for (int n = blockIdx.y; n < r0p; n += gridDim.y) {
        long base = (long)((n & 1) * TLEN + (n >> 1)) * OUTN;
        float v;
        if (n < r0) {
            const float4* wr = (const float4*)(W_lin + c * 64);
            const float4* hv = (const float4*)(g_h1 + n * 64);
            float acc = b_lin[c];
#pragma unroll
            for (int j = 0; j < 16; ++j) {
                float4 w = __ldg(wr + j);
                float4 h = __ldg(hv + j);
                acc = fmaf(w.x, h.x, acc);
                acc = fmaf(w.y, h.y, acc);
                acc = fmaf(w.z, h.z, acc);
                acc = fmaf(w.w, h.w, acc);
            }
            v = acc;
        } else {
            v = ((n & 1) == ip) ? g_yA[c] : g_yB[c];
        }
        out[base + c] = v;
    }
}

// ---------------------------------------------------------------------------
// Broadcast-fill. Within half s, every row has n&1 == s, so the whole half
// is ONE vector repeated. 4 consecutive rows (t0 % 4 == 0) form a 16B-aligned
// contiguous span of 4*OUTN floats whose content is ys[f mod OUTN]: one
// aligned STG.128 per 16B, mod via compare-subtract, smem source (+3 dup).
// ---------------------------------------------------------------------------
__global__ void __launch_bounds__(256) fill_out(float* __restrict__ out)
{
    const int r0 = g_r0;
    int r0p = (r0 + 7) & ~7;
    if (r0p > NSUB) r0p = NSUB;
    const int Tc = r0p >> 1;              // multiple of 4

    const int t0 = blockIdx.x * 4;
    if (t0 < Tc) return;
    const int s = blockIdx.y;

    __shared__ __align__(16) float ysd[OUTN + 3];
    const float* y = (s == g_ipar) ? g_yA : g_yB;
    for (int i = threadIdx.x; i < OUTN; i += 256) ysd[i] = __ldg(y + i);
    if (threadIdx.x < 3) ysd[OUTN + threadIdx.x] = __ldg(y + threadIdx.x);
    __syncthreads();

    long base = (long)(s * TLEN + t0) * OUTN;      // t0%4==0 -> 16B aligned
    float4* dst = (float4*)(out + base);
    for (int q = threadIdx.x; q < OUTN; q += 256) {  // 4761 float4 = 4 rows
        int f = 4 * q;
        int m = f;
        if (m >= 3 * OUTN)      m -= 3 * OUTN;
        else if (m >= 2 * OUTN) m -= 2 * OUTN;
        else if (m >= OUTN)     m -= OUTN;
        float4 v = make_float4(ysd[m], ysd[m + 1], ysd[m + 2], ysd[m + 3]);
        __stcs(dst + q, v);
    }
}

// ---------------------------------------------------------------------------
extern "C" void kernel_launch(void* const* d_in, const int* in_sizes, int n_in,
                              void* d_out, int out_size)
{
    (void)in_sizes; (void)n_in; (void)out_size;
    const float* hidden = (const float*)d_in[0];
    // d_in[1] = W_ih0: unused (RNN input is identically zero)
    const float* W_hh0  = (const float*)d_in[2];
    const float* b_ih0  = (const float*)d_in[3];
    const float* b_hh0  = (const float*)d_in[4];
    const float* W_ih1  = (const float*)d_in[5];
    const float* W_hh1  = (const float*)d_in[6];
    const float* b_ih1  = (const float*)d_in[7];
    const float* b_hh1  = (const float*)d_in[8];
    const float* W_lin  = (const float*)d_in[9];
    const float* b_lin  = (const float*)d_in[10];
    float* out = (float*)d_out;

    rnn_phase1<<<1, 256>>>(hidden, W_hh0, b_ih0, b_hh0,
                           W_ih1, W_hh1, b_ih1, b_hh1);

    yab_kernel<<<(2 * OUTN + 255) / 256, 256>>>(W_lin, b_lin);

    dim3 hgrid(19, 64);
    head_kernel<<<hgrid, 256>>>(W_lin, b_lin, out);

    dim3 fgrid(TLEN / 4, 2);
    fill_out<<<fgrid, 256>>>(out);
}